// round 1
// baseline (speedup 1.0000x reference)
#include <cuda_runtime.h>
#include <math.h>

#define N_EXP 8
#define CDIM  1024
#define MAX_T 8192

// scratch (no allocation allowed -> __device__ globals)
__device__ float g_p1[MAX_T];
__device__ float g_p2[MAX_T];
__device__ int   g_e1[MAX_T];
__device__ int   g_e2[MAX_T];
__device__ int   g_r1[MAX_T];
__device__ int   g_r2[MAX_T];

// ---------------------------------------------------------------------------
// Kernel 1: gating GEMV + top-2 + masked softmax (warp per token)
// ---------------------------------------------------------------------------
__global__ void gate_kernel(const float* __restrict__ x,
                            const float* __restrict__ wg,
                            int T)
{
    int warp = (blockIdx.x * blockDim.x + threadIdx.x) >> 5;
    int lane = threadIdx.x & 31;
    if (warp >= T) return;

    const float* xr = x + (size_t)warp * CDIM;
    float acc[N_EXP];
#pragma unroll
    for (int e = 0; e < N_EXP; e++) acc[e] = 0.f;

    // coalesced x loads; wg (32 KB) stays hot in L1 and broadcasts
    for (int c = lane; c < CDIM; c += 32) {
        float xv = xr[c];
#pragma unroll
        for (int e = 0; e < N_EXP; e++)
            acc[e] += xv * wg[e * CDIM + c];
    }
#pragma unroll
    for (int e = 0; e < N_EXP; e++) {
#pragma unroll
        for (int o = 16; o > 0; o >>= 1)
            acc[e] += __shfl_xor_sync(0xffffffffu, acc[e], o);
    }

    if (lane == 0) {
        // top-1 (first max on ties, matching lax.top_k)
        int e1 = 0; float l1 = acc[0];
#pragma unroll
        for (int e = 1; e < N_EXP; e++)
            if (acc[e] > l1) { l1 = acc[e]; e1 = e; }
        // top-2
        int e2 = -1; float l2 = -INFINITY;
#pragma unroll
        for (int e = 0; e < N_EXP; e++)
            if (e != e1 && acc[e] > l2) { l2 = acc[e]; e2 = e; }

        // softmax over {l1, l2} (others are -inf). l2 <= l1 so this is stable.
        float p1 = 1.f / (1.f + expf(l2 - l1));
        float p2 = 1.f - p1;

        g_e1[warp] = e1; g_e2[warp] = e2;
        g_p1[warp] = p1; g_p2[warp] = p2;
    }
}

// ---------------------------------------------------------------------------
// Kernel 2: k-major cumulative ranks + used_capacity. Single block.
// Ordering: all k=0 assignments (token order), then all k=1 assignments.
// ---------------------------------------------------------------------------
__global__ void rank_kernel(int T, int cap, float* __restrict__ out_used)
{
    __shared__ int s1[256 * N_EXP];
    __shared__ int s2[256 * N_EXP];
    __shared__ int tot1[N_EXP];

    int tid = threadIdx.x;
    int per = (T + 255) / 256;
    int base = tid * per;
    int end  = min(base + per, T);

    int c1[N_EXP], c2[N_EXP];
#pragma unroll
    for (int e = 0; e < N_EXP; e++) { c1[e] = 0; c2[e] = 0; }
    for (int t = base; t < end; t++) { c1[g_e1[t]]++; c2[g_e2[t]]++; }
#pragma unroll
    for (int e = 0; e < N_EXP; e++) {
        s1[tid * N_EXP + e] = c1[e];
        s2[tid * N_EXP + e] = c2[e];
    }
    __syncthreads();

    if (tid == 0) {
        int r1[N_EXP], r2[N_EXP];
#pragma unroll
        for (int e = 0; e < N_EXP; e++) { r1[e] = 0; r2[e] = 0; }
        for (int t = 0; t < 256; t++) {
#pragma unroll
            for (int e = 0; e < N_EXP; e++) {
                int a = s1[t * N_EXP + e]; s1[t * N_EXP + e] = r1[e]; r1[e] += a;
                int b = s2[t * N_EXP + e]; s2[t * N_EXP + e] = r2[e]; r2[e] += b;
            }
        }
#pragma unroll
        for (int e = 0; e < N_EXP; e++) {
            tot1[e] = r1[e];
            int total = r1[e] + r2[e];
            out_used[e] = (float)min(total, cap);   // used_capacity
        }
    }
    __syncthreads();

    int o1[N_EXP], o2[N_EXP];
#pragma unroll
    for (int e = 0; e < N_EXP; e++) {
        o1[e] = s1[tid * N_EXP + e];
        o2[e] = tot1[e] + s2[tid * N_EXP + e];   // k=1 ranks start after all k=0
    }
    for (int t = base; t < end; t++) {
        int e = g_e1[t]; g_r1[t] = o1[e]; o1[e]++;
        e     = g_e2[t]; g_r2[t] = o2[e]; o2[e]++;
    }
}

// ---------------------------------------------------------------------------
// Kernel 3: scatter ≤2 (weight, mask) pairs per token into zeroed output
// ---------------------------------------------------------------------------
__global__ void scatter_kernel(float* __restrict__ cb,
                               float* __restrict__ mask,
                               int T, int cap)
{
    int t = blockIdx.x * blockDim.x + threadIdx.x;
    if (t >= T) return;
    size_t row = (size_t)t * N_EXP * cap;

    int r1 = g_r1[t];
    if (r1 < cap) {
        float p = g_p1[t];
        size_t o = row + (size_t)g_e1[t] * cap + r1;
        cb[o] = p;
        if (p != 0.f) mask[o] = 1.f;
    }
    int r2 = g_r2[t];
    if (r2 < cap) {
        float p = g_p2[t];
        size_t o = row + (size_t)g_e2[t] * cap + r2;
        cb[o] = p;
        if (p != 0.f) mask[o] = 1.f;
    }
}

// ---------------------------------------------------------------------------
extern "C" void kernel_launch(void* const* d_in, const int* in_sizes, int n_in,
                              void* d_out, int out_size)
{
    const float* x  = (const float*)d_in[0];
    const float* wg = (const float*)d_in[1];

    int T = in_sizes[0] / CDIM;                       // 4096
    // out layout: [used_capacity(8) | cb_weight(T*E*cap) | sec_mask(T*E*cap)]
    long long rest = (long long)out_size - N_EXP;
    int cap = (int)(rest / (2LL * T * N_EXP));        // 2048

    float* out_used = (float*)d_out;
    float* cb       = out_used + N_EXP;
    float* mask     = cb + (size_t)T * N_EXP * cap;

    // zero everything (output is poisoned); HW fill ≈ the HBM-write floor
    cudaMemsetAsync(d_out, 0, (size_t)out_size * sizeof(float), 0);

    // gating: 8 warps/block
    int warps_per_block = 8;
    int blocks = (T + warps_per_block - 1) / warps_per_block;
    gate_kernel<<<blocks, warps_per_block * 32>>>(x, wg, T);

    rank_kernel<<<1, 256>>>(T, cap, out_used);

    scatter_kernel<<<(T + 255) / 256, 256>>>(cb, mask, T, cap);
}